// round 1
// baseline (speedup 1.0000x reference)
#include <cuda_runtime.h>
#include <math.h>

#define N_NODES 100000
#define HIDDEN  128
#define NFILT   64
#define CUTOFF  8.0f
#define TABLE_N 8192
#define BM      64
#define SA_STRIDE 132   // 128 + 4: keeps 16B alignment for float4, avoids bank conflicts

// ---- device scratch (allocation-free) ----
__device__ float g_agg[N_NODES * HIDDEN];   // segment-sum accumulator (51.2 MB)
__device__ float g_table[TABLE_N];          // fsum(w) lookup table
__device__ float g_wsum[NFILT];
__device__ float g_bsum;
__device__ float g_oscale[HIDDEN];          // folded BN scale
__device__ float g_oshift[HIDDEN];          // folded bi2 + BN shift

// ---- packed f32x2 helpers (B300 FFMA2) ----
__device__ __forceinline__ unsigned long long pk2(float lo, float hi) {
    unsigned long long r;
    asm("mov.b64 %0, {%1, %2};" : "=l"(r) : "f"(lo), "f"(hi));
    return r;
}
__device__ __forceinline__ float2 upk2(unsigned long long v) {
    float2 f;
    asm("mov.b64 {%0, %1}, %2;" : "=f"(f.x), "=f"(f.y) : "l"(v));
    return f;
}
__device__ __forceinline__ unsigned long long ffma2(unsigned long long a,
                                                    unsigned long long b,
                                                    unsigned long long c) {
    unsigned long long d;
    asm("fma.rn.f32x2 %0, %1, %2, %3;" : "=l"(d) : "l"(a), "l"(b), "l"(c));
    return d;
}

__device__ __forceinline__ void red_add_v4(float4* addr, float4 v) {
    asm volatile("red.global.add.v4.f32 [%0], {%1, %2, %3, %4};"
                 :: "l"(addr), "f"(v.x), "f"(v.y), "f"(v.z), "f"(v.w)
                 : "memory");
}

__device__ __forceinline__ float softplus_f(float x) {
    // jax.nn.softplus = max(x,0) + log1p(exp(-|x|))
    return log1pf(expf(-fabsf(x))) + fmaxf(x, 0.f);
}

// ---- kernel 1: zero the accumulator ----
__global__ void zero_kernel() {
    const int n4 = N_NODES * HIDDEN / 4;
    float4 z = make_float4(0.f, 0.f, 0.f, 0.f);
    for (int i = blockIdx.x * blockDim.x + threadIdx.x; i < n4;
         i += gridDim.x * blockDim.x)
        ((float4*)g_agg)[i] = z;
}

// ---- kernel 2: tiny precompute (wsum, bsum, BN folding) ----
__global__ void prep_kernel(const float* __restrict__ Wf2,
                            const float* __restrict__ bf2,
                            const float* __restrict__ bi2,
                            const float* __restrict__ gamma,
                            const float* __restrict__ beta,
                            const float* __restrict__ mmean,
                            const float* __restrict__ mvar) {
    int t = threadIdx.x;
    if (t < NFILT) {
        float s = 0.f;
        for (int f = 0; f < NFILT; f++) s += Wf2[t * NFILT + f];
        g_wsum[t] = s;
    }
    if (t == 0) {
        float s = 0.f;
        for (int f = 0; f < NFILT; f++) s += bf2[f];
        g_bsum = s;
    }
    if (t < HIDDEN) {
        float sc = gamma[t] * rsqrtf(mvar[t] + 1e-3f);
        g_oscale[t] = sc;
        g_oshift[t] = (bi2[t] - mmean[t]) * sc + beta[t];
    }
}

// ---- kernel 3: build fsum(w) table over w in [0, CUTOFF] ----
__global__ void table_kernel(const float* __restrict__ Wf1,
                             const float* __restrict__ bf1) {
    int t = blockIdx.x * blockDim.x + threadIdx.x;
    if (t >= TABLE_N) return;
    float w  = (float)t * (CUTOFF / (float)(TABLE_N - 1));
    float sc = w * (2.0f / CUTOFF) - 1.0f;
    float s  = g_bsum;
    #pragma unroll 8
    for (int g = 0; g < NFILT; g++)
        s += tanhf(sc * __ldg(&Wf1[g]) + __ldg(&bf1[g])) * g_wsum[g];
    float cut = 0.5f * (cospif(w * (1.0f / CUTOFF)) + 1.0f);
    g_table[t] = s * cut;
}

// ---- kernel 4: gather x[col]*fsum, scatter-add into agg[row] ----
// one warp per edge; each lane owns one float4 (32*16B = 512B row)
__global__ void scatter_kernel(const float* __restrict__ x,
                               const int* __restrict__ ei,
                               const float* __restrict__ ew,
                               int E) {
    int e    = blockIdx.x * (blockDim.x >> 5) + (threadIdx.x >> 5);
    int lane = threadIdx.x & 31;
    if (e >= E) return;

    float w = __ldg(&ew[e]);
    float fs = 0.f;
    if (w <= CUTOFF) {
        float u = w * ((float)(TABLE_N - 1) / CUTOFF);
        int   i = (int)u;
        if (i > TABLE_N - 2) i = TABLE_N - 2;
        float fr = u - (float)i;
        float t0 = g_table[i];
        fs = t0 + fr * (g_table[i + 1] - t0);
    }
    if (fs != 0.f) {
        int row = __ldg(&ei[e]);
        int col = __ldg(&ei[E + e]);
        float4 v = ((const float4*)x)[col * 32 + lane];
        v.x *= fs; v.y *= fs; v.z *= fs; v.w *= fs;
        red_add_v4(((float4*)g_agg) + row * 32 + lane, v);
    }
}

// ---- kernel 5: fused MLP + BN ----
// out = BN(softplus(agg@Wi1 + bi1) @ Wi2 + bi2)
// 64 rows/block, 256 threads (16x16), each thread: 4 rows x 8 cols (4 f32x2 pairs)
__global__ __launch_bounds__(256) void mlp_kernel(
    const float* __restrict__ Wi1, const float* __restrict__ bi1,
    const float* __restrict__ Wi2, float* __restrict__ out) {
    extern __shared__ float sm[];
    float* sA = sm;                         // BM * SA_STRIDE
    float* sW = sm + BM * SA_STRIDE;        // 128 * 128

    int tid = threadIdx.x;
    int tx = tid & 15, ty = tid >> 4;
    int rb = blockIdx.x * BM;

    // load A tile (zero-pad tail rows)
    for (int i = tid; i < BM * 32; i += 256) {
        int r = i >> 5, c4 = i & 31;
        float4 v = make_float4(0.f, 0.f, 0.f, 0.f);
        if (rb + r < N_NODES) v = ((const float4*)g_agg)[(rb + r) * 32 + c4];
        *(float4*)&sA[r * SA_STRIDE + c4 * 4] = v;
    }
    // load Wi1
    for (int i = tid; i < 128 * 32; i += 256)
        ((float4*)sW)[i] = ((const float4*)Wi1)[i];
    __syncthreads();

    unsigned long long acc[4][4];
    {
        const float2* bp = (const float2*)&bi1[tx * 8];
        #pragma unroll
        for (int j = 0; j < 4; j++) {
            float2 b = bp[j];
            unsigned long long v = pk2(b.x, b.y);
            acc[0][j] = v; acc[1][j] = v; acc[2][j] = v; acc[3][j] = v;
        }
    }
    #pragma unroll 4
    for (int k = 0; k < 128; k++) {
        unsigned long long av[4];
        #pragma unroll
        for (int r = 0; r < 4; r++) {
            float a = sA[(ty * 4 + r) * SA_STRIDE + k];
            av[r] = pk2(a, a);
        }
        const ulonglong2* wp = (const ulonglong2*)&sW[k * 128 + tx * 8];
        ulonglong2 b01 = wp[0], b23 = wp[1];
        unsigned long long bv[4] = {b01.x, b01.y, b23.x, b23.y};
        #pragma unroll
        for (int r = 0; r < 4; r++)
            #pragma unroll
            for (int j = 0; j < 4; j++)
                acc[r][j] = ffma2(av[r], bv[j], acc[r][j]);
    }
    __syncthreads();

    // softplus -> write H back into sA; load Wi2 over Wi1
    #pragma unroll
    for (int r = 0; r < 4; r++)
        #pragma unroll
        for (int j = 0; j < 4; j++) {
            float2 h = upk2(acc[r][j]);
            float* p = &sA[(ty * 4 + r) * SA_STRIDE + tx * 8 + j * 2];
            p[0] = softplus_f(h.x);
            p[1] = softplus_f(h.y);
        }
    for (int i = tid; i < 128 * 32; i += 256)
        ((float4*)sW)[i] = ((const float4*)Wi2)[i];
    __syncthreads();

    #pragma unroll
    for (int r = 0; r < 4; r++)
        #pragma unroll
        for (int j = 0; j < 4; j++) acc[r][j] = 0ULL;

    #pragma unroll 4
    for (int k = 0; k < 128; k++) {
        unsigned long long av[4];
        #pragma unroll
        for (int r = 0; r < 4; r++) {
            float a = sA[(ty * 4 + r) * SA_STRIDE + k];
            av[r] = pk2(a, a);
        }
        const ulonglong2* wp = (const ulonglong2*)&sW[k * 128 + tx * 8];
        ulonglong2 b01 = wp[0], b23 = wp[1];
        unsigned long long bv[4] = {b01.x, b01.y, b23.x, b23.y};
        #pragma unroll
        for (int r = 0; r < 4; r++)
            #pragma unroll
            for (int j = 0; j < 4; j++)
                acc[r][j] = ffma2(av[r], bv[j], acc[r][j]);
    }

    // epilogue: BN (bias folded into g_oshift)
    #pragma unroll
    for (int j = 0; j < 4; j++) {
        int c = tx * 8 + j * 2;
        float2 sc = *(const float2*)&g_oscale[c];
        float2 sh = *(const float2*)&g_oshift[c];
        #pragma unroll
        for (int r = 0; r < 4; r++) {
            int gr = rb + ty * 4 + r;
            if (gr < N_NODES) {
                float2 h = upk2(acc[r][j]);
                float2 o = make_float2(h.x * sc.x + sh.x, h.y * sc.y + sh.y);
                *(float2*)&out[gr * 128 + c] = o;
            }
        }
    }
}

extern "C" void kernel_launch(void* const* d_in, const int* in_sizes, int n_in,
                              void* d_out, int out_size) {
    const float* x     = (const float*)d_in[0];
    const int*   ei    = (const int*)  d_in[1];
    const float* ew    = (const float*)d_in[2];
    // d_in[3] = edge_attr (unused by the reference math)
    const float* Wf1   = (const float*)d_in[4];
    const float* bf1   = (const float*)d_in[5];
    const float* Wf2   = (const float*)d_in[6];
    const float* bf2   = (const float*)d_in[7];
    const float* Wi1   = (const float*)d_in[8];
    const float* bi1   = (const float*)d_in[9];
    const float* Wi2   = (const float*)d_in[10];
    const float* bi2   = (const float*)d_in[11];
    const float* gamma = (const float*)d_in[12];
    const float* beta  = (const float*)d_in[13];
    const float* mmean = (const float*)d_in[14];
    const float* mvar  = (const float*)d_in[15];
    int E = in_sizes[2];
    float* out = (float*)d_out;

    zero_kernel<<<4096, 256>>>();
    prep_kernel<<<1, 128>>>(Wf2, bf2, bi2, gamma, beta, mmean, mvar);
    table_kernel<<<TABLE_N / 256, 256>>>(Wf1, bf1);
    scatter_kernel<<<(E + 7) / 8, 256>>>(x, ei, ew, E);

    int smem_bytes = (BM * SA_STRIDE + 128 * 128) * (int)sizeof(float);
    cudaFuncSetAttribute(mlp_kernel, cudaFuncAttributeMaxDynamicSharedMemorySize,
                         smem_bytes);
    mlp_kernel<<<(N_NODES + BM - 1) / BM, 256, smem_bytes>>>(Wi1, bi1, Wi2, out);
}

// round 2
// speedup vs baseline: 1.2459x; 1.2459x over previous
#include <cuda_runtime.h>
#include <math.h>

#define N_NODES 100000
#define HIDDEN  128
#define NFILT   64
#define CUTOFF  8.0f
#define TABLE_N 8192
#define BM      64
#define SA_STRIDE 132   // 128 + 4: keeps 16B alignment for float4, avoids bank conflicts
#define EPW     8       // edges per warp batch

// ---- device scratch (allocation-free) ----
__device__ float g_agg[N_NODES * HIDDEN];   // segment-sum accumulator (51.2 MB)
__device__ float g_table[TABLE_N];          // fsum(w) lookup table
__device__ float g_wsum[NFILT];
__device__ float g_bsum;
__device__ float g_oscale[HIDDEN];          // folded BN scale
__device__ float g_oshift[HIDDEN];          // folded bi2 + BN shift

// ---- packed f32x2 helpers (B300 FFMA2) ----
__device__ __forceinline__ unsigned long long pk2(float lo, float hi) {
    unsigned long long r;
    asm("mov.b64 %0, {%1, %2};" : "=l"(r) : "f"(lo), "f"(hi));
    return r;
}
__device__ __forceinline__ float2 upk2(unsigned long long v) {
    float2 f;
    asm("mov.b64 {%0, %1}, %2;" : "=f"(f.x), "=f"(f.y) : "l"(v));
    return f;
}
__device__ __forceinline__ unsigned long long ffma2(unsigned long long a,
                                                    unsigned long long b,
                                                    unsigned long long c) {
    unsigned long long d;
    asm("fma.rn.f32x2 %0, %1, %2, %3;" : "=l"(d) : "l"(a), "l"(b), "l"(c));
    return d;
}

__device__ __forceinline__ void red_add_v4(float4* addr, float4 v) {
    asm volatile("red.global.add.v4.f32 [%0], {%1, %2, %3, %4};"
                 :: "l"(addr), "f"(v.x), "f"(v.y), "f"(v.z), "f"(v.w)
                 : "memory");
}

__device__ __forceinline__ float softplus_f(float x) {
    // jax.nn.softplus = max(x,0) + log1p(exp(-|x|))
    return log1pf(expf(-fabsf(x))) + fmaxf(x, 0.f);
}

// ---- kernel 1: zero the accumulator ----
__global__ void zero_kernel() {
    const int n4 = N_NODES * HIDDEN / 4;
    float4 z = make_float4(0.f, 0.f, 0.f, 0.f);
    for (int i = blockIdx.x * blockDim.x + threadIdx.x; i < n4;
         i += gridDim.x * blockDim.x)
        ((float4*)g_agg)[i] = z;
}

// ---- kernel 2: tiny precompute (wsum, bsum, BN folding) ----
__global__ void prep_kernel(const float* __restrict__ Wf2,
                            const float* __restrict__ bf2,
                            const float* __restrict__ bi2,
                            const float* __restrict__ gamma,
                            const float* __restrict__ beta,
                            const float* __restrict__ mmean,
                            const float* __restrict__ mvar) {
    int t = threadIdx.x;
    if (t < NFILT) {
        float s = 0.f;
        for (int f = 0; f < NFILT; f++) s += Wf2[t * NFILT + f];
        g_wsum[t] = s;
    }
    if (t == 0) {
        float s = 0.f;
        for (int f = 0; f < NFILT; f++) s += bf2[f];
        g_bsum = s;
    }
    if (t < HIDDEN) {
        float sc = gamma[t] * rsqrtf(mvar[t] + 1e-3f);
        g_oscale[t] = sc;
        g_oshift[t] = (bi2[t] - mmean[t]) * sc + beta[t];
    }
}

// ---- kernel 3: build fsum(w) table over w in [0, CUTOFF] ----
__global__ void table_kernel(const float* __restrict__ Wf1,
                             const float* __restrict__ bf1) {
    int t = blockIdx.x * blockDim.x + threadIdx.x;
    if (t >= TABLE_N) return;
    float w  = (float)t * (CUTOFF / (float)(TABLE_N - 1));
    float sc = w * (2.0f / CUTOFF) - 1.0f;
    float s  = g_bsum;
    #pragma unroll 8
    for (int g = 0; g < NFILT; g++)
        s += tanhf(sc * __ldg(&Wf1[g]) + __ldg(&bf1[g])) * g_wsum[g];
    float cut = 0.5f * (cospif(w * (1.0f / CUTOFF)) + 1.0f);
    g_table[t] = s * cut;
}

// ---- kernel 4: gather x[col]*fsum, scatter-add into agg[row] ----
// one warp handles EPW edges per batch; lanes 0..EPW-1 fetch metadata,
// shfl-broadcast, then 8 independent gathers followed by 8 reds.
__global__ __launch_bounds__(256) void scatter_kernel(
        const float* __restrict__ x,
        const int* __restrict__ ei,
        const float* __restrict__ ew,
        int E) {
    int gw   = (blockIdx.x * blockDim.x + threadIdx.x) >> 5;
    int nw   = (gridDim.x * blockDim.x) >> 5;
    int lane = threadIdx.x & 31;

    for (int e0 = gw * EPW; e0 < E; e0 += nw * EPW) {
        int n = E - e0; if (n > EPW) n = EPW;

        float fs = 0.f; int row = 0, col = 0;
        if (lane < n) {
            float w = __ldg(&ew[e0 + lane]);
            row = __ldg(&ei[e0 + lane]);
            col = __ldg(&ei[E + e0 + lane]);
            float u = w * ((float)(TABLE_N - 1) / CUTOFF);
            int   i = (int)u;
            if (i > TABLE_N - 2) i = TABLE_N - 2;
            float fr = u - (float)i;
            float t0 = g_table[i];
            fs = (w <= CUTOFF) ? (t0 + fr * (g_table[i + 1] - t0)) : 0.f;
        }

        float4 v[EPW]; int rows[EPW]; float fss[EPW];
        #pragma unroll
        for (int j = 0; j < EPW; j++) {
            int   c = __shfl_sync(0xFFFFFFFFu, col, j);
            rows[j] = __shfl_sync(0xFFFFFFFFu, row, j);
            fss[j]  = __shfl_sync(0xFFFFFFFFu, fs,  j);
            if (j < n)
                v[j] = ((const float4*)x)[c * 32 + lane];
        }
        #pragma unroll
        for (int j = 0; j < EPW; j++) {
            if (j < n && fss[j] != 0.f) {
                float4 t = v[j];
                float  f = fss[j];
                t.x *= f; t.y *= f; t.z *= f; t.w *= f;
                red_add_v4(((float4*)g_agg) + rows[j] * 32 + lane, t);
            }
        }
    }
}

// ---- kernel 5: fused MLP + BN ----
// out = BN(softplus(agg@Wi1 + bi1) @ Wi2 + bi2)
// 64 rows/block, 256 threads (16x16), each thread: 4 rows x 8 cols (4 f32x2 pairs)
__global__ __launch_bounds__(256) void mlp_kernel(
    const float* __restrict__ Wi1, const float* __restrict__ bi1,
    const float* __restrict__ Wi2, float* __restrict__ out) {
    extern __shared__ float sm[];
    float* sA = sm;                         // BM * SA_STRIDE
    float* sW = sm + BM * SA_STRIDE;        // 128 * 128

    int tid = threadIdx.x;
    int tx = tid & 15, ty = tid >> 4;
    int rb = blockIdx.x * BM;

    // load A tile (zero-pad tail rows)
    for (int i = tid; i < BM * 32; i += 256) {
        int r = i >> 5, c4 = i & 31;
        float4 v = make_float4(0.f, 0.f, 0.f, 0.f);
        if (rb + r < N_NODES) v = ((const float4*)g_agg)[(rb + r) * 32 + c4];
        *(float4*)&sA[r * SA_STRIDE + c4 * 4] = v;
    }
    // load Wi1
    for (int i = tid; i < 128 * 32; i += 256)
        ((float4*)sW)[i] = ((const float4*)Wi1)[i];
    __syncthreads();

    unsigned long long acc[4][4];
    {
        const float2* bp = (const float2*)&bi1[tx * 8];
        #pragma unroll
        for (int j = 0; j < 4; j++) {
            float2 b = bp[j];
            unsigned long long v = pk2(b.x, b.y);
            acc[0][j] = v; acc[1][j] = v; acc[2][j] = v; acc[3][j] = v;
        }
    }
    #pragma unroll 2
    for (int k4 = 0; k4 < 128; k4 += 4) {
        float4 a4[4];
        #pragma unroll
        for (int r = 0; r < 4; r++)
            a4[r] = *(const float4*)&sA[(ty * 4 + r) * SA_STRIDE + k4];
        #pragma unroll
        for (int kk = 0; kk < 4; kk++) {
            unsigned long long av[4];
            #pragma unroll
            for (int r = 0; r < 4; r++) {
                float a = (kk == 0) ? a4[r].x : (kk == 1) ? a4[r].y
                        : (kk == 2) ? a4[r].z : a4[r].w;
                av[r] = pk2(a, a);
            }
            const ulonglong2* wp = (const ulonglong2*)&sW[(k4 + kk) * 128 + tx * 8];
            ulonglong2 b01 = wp[0], b23 = wp[1];
            unsigned long long bv[4] = {b01.x, b01.y, b23.x, b23.y};
            #pragma unroll
            for (int r = 0; r < 4; r++)
                #pragma unroll
                for (int j = 0; j < 4; j++)
                    acc[r][j] = ffma2(av[r], bv[j], acc[r][j]);
        }
    }
    __syncthreads();

    // softplus -> write H back into sA; load Wi2 over Wi1
    #pragma unroll
    for (int r = 0; r < 4; r++) {
        float4 h01, h23;
        float2 a = upk2(acc[r][0]), b = upk2(acc[r][1]);
        float2 c = upk2(acc[r][2]), d = upk2(acc[r][3]);
        h01 = make_float4(softplus_f(a.x), softplus_f(a.y),
                          softplus_f(b.x), softplus_f(b.y));
        h23 = make_float4(softplus_f(c.x), softplus_f(c.y),
                          softplus_f(d.x), softplus_f(d.y));
        float* p = &sA[(ty * 4 + r) * SA_STRIDE + tx * 8];
        *(float4*)(p)     = h01;
        *(float4*)(p + 4) = h23;
    }
    for (int i = tid; i < 128 * 32; i += 256)
        ((float4*)sW)[i] = ((const float4*)Wi2)[i];
    __syncthreads();

    #pragma unroll
    for (int r = 0; r < 4; r++)
        #pragma unroll
        for (int j = 0; j < 4; j++) acc[r][j] = 0ULL;

    #pragma unroll 2
    for (int k4 = 0; k4 < 128; k4 += 4) {
        float4 a4[4];
        #pragma unroll
        for (int r = 0; r < 4; r++)
            a4[r] = *(const float4*)&sA[(ty * 4 + r) * SA_STRIDE + k4];
        #pragma unroll
        for (int kk = 0; kk < 4; kk++) {
            unsigned long long av[4];
            #pragma unroll
            for (int r = 0; r < 4; r++) {
                float a = (kk == 0) ? a4[r].x : (kk == 1) ? a4[r].y
                        : (kk == 2) ? a4[r].z : a4[r].w;
                av[r] = pk2(a, a);
            }
            const ulonglong2* wp = (const ulonglong2*)&sW[(k4 + kk) * 128 + tx * 8];
            ulonglong2 b01 = wp[0], b23 = wp[1];
            unsigned long long bv[4] = {b01.x, b01.y, b23.x, b23.y};
            #pragma unroll
            for (int r = 0; r < 4; r++)
                #pragma unroll
                for (int j = 0; j < 4; j++)
                    acc[r][j] = ffma2(av[r], bv[j], acc[r][j]);
        }
    }

    // epilogue: BN (bias folded into g_oshift), float4 stores (8 contiguous cols)
    int c0 = tx * 8;
    float4 sc0 = *(const float4*)&g_oscale[c0];
    float4 sc1 = *(const float4*)&g_oscale[c0 + 4];
    float4 sh0 = *(const float4*)&g_oshift[c0];
    float4 sh1 = *(const float4*)&g_oshift[c0 + 4];
    #pragma unroll
    for (int r = 0; r < 4; r++) {
        int gr = rb + ty * 4 + r;
        if (gr < N_NODES) {
            float2 a = upk2(acc[r][0]), b = upk2(acc[r][1]);
            float2 c = upk2(acc[r][2]), d = upk2(acc[r][3]);
            float4 o0 = make_float4(a.x * sc0.x + sh0.x, a.y * sc0.y + sh0.y,
                                    b.x * sc0.z + sh0.z, b.y * sc0.w + sh0.w);
            float4 o1 = make_float4(c.x * sc1.x + sh1.x, c.y * sc1.y + sh1.y,
                                    d.x * sc1.z + sh1.z, d.y * sc1.w + sh1.w);
            *(float4*)&out[gr * 128 + c0]     = o0;
            *(float4*)&out[gr * 128 + c0 + 4] = o1;
        }
    }
}

extern "C" void kernel_launch(void* const* d_in, const int* in_sizes, int n_in,
                              void* d_out, int out_size) {
    const float* x     = (const float*)d_in[0];
    const int*   ei    = (const int*)  d_in[1];
    const float* ew    = (const float*)d_in[2];
    // d_in[3] = edge_attr (unused by the reference math)
    const float* Wf1   = (const float*)d_in[4];
    const float* bf1   = (const float*)d_in[5];
    const float* Wf2   = (const float*)d_in[6];
    const float* bf2   = (const float*)d_in[7];
    const float* Wi1   = (const float*)d_in[8];
    const float* bi1   = (const float*)d_in[9];
    const float* Wi2   = (const float*)d_in[10];
    const float* bi2   = (const float*)d_in[11];
    const float* gamma = (const float*)d_in[12];
    const float* beta  = (const float*)d_in[13];
    const float* mmean = (const float*)d_in[14];
    const float* mvar  = (const float*)d_in[15];
    int E = in_sizes[2];
    float* out = (float*)d_out;

    zero_kernel<<<4096, 256>>>();
    prep_kernel<<<1, 128>>>(Wf2, bf2, bi2, gamma, beta, mmean, mvar);
    table_kernel<<<TABLE_N / 256, 256>>>(Wf1, bf1);
    scatter_kernel<<<1184, 256>>>(x, ei, ew, E);   // 148 SMs x 8 blocks: one wave

    int smem_bytes = (BM * SA_STRIDE + 128 * 128) * (int)sizeof(float);
    cudaFuncSetAttribute(mlp_kernel, cudaFuncAttributeMaxDynamicSharedMemorySize,
                         smem_bytes);
    mlp_kernel<<<(N_NODES + BM - 1) / BM, 256, smem_bytes>>>(Wi1, bi1, Wi2, out);
}

// round 4
// speedup vs baseline: 1.9903x; 1.5975x over previous
#include <cuda_runtime.h>
#include <cuda_bf16.h>
#include <math.h>
#include <stdint.h>

#define N_NODES 100000
#define HIDDEN  128
#define NFILT   64
#define CUTOFF  8.0f
#define TABLE_N 8192
#define EPW     8
#define N_TILES ((N_NODES + 127) / 128)  // 782
#define LDW     136                      // smem bf16 row stride (odd 16B chunks -> conflict-free ldmatrix)

// ---- device scratch (allocation-free) ----
__device__ __align__(16) float g_agg[N_NODES * HIDDEN];
__device__ float g_table[TABLE_N];
__device__ float g_wsum[NFILT];
__device__ float g_bsum;
__device__ float g_oscale[HIDDEN];
__device__ float g_oshift[HIDDEN];
// compensated bf16 weights, transposed: [n][k] with k contiguous
__device__ __align__(16) __nv_bfloat16 g_W1h[HIDDEN * HIDDEN];
__device__ __align__(16) __nv_bfloat16 g_W1l[HIDDEN * HIDDEN];
__device__ __align__(16) __nv_bfloat16 g_W2h[HIDDEN * HIDDEN];
__device__ __align__(16) __nv_bfloat16 g_W2l[HIDDEN * HIDDEN];

// ================= helpers =================
__device__ __forceinline__ uint32_t smem_u32(const void* p) {
    uint32_t a;
    asm("{ .reg .u64 t; cvta.to.shared.u64 t, %1; cvt.u32.u64 %0, t; }" : "=r"(a) : "l"(p));
    return a;
}
__device__ __forceinline__ uint32_t bf2pack(float x0, float x1) {
    uint32_t p;  // lower half = x0
    asm("cvt.rn.bf16x2.f32 %0, %1, %2;" : "=r"(p) : "f"(x1), "f"(x0));
    return p;
}
__device__ __forceinline__ float softplus_f(float x) {
    return log1pf(expf(-fabsf(x))) + fmaxf(x, 0.f);
}
__device__ __forceinline__ void red_add_v4(float4* addr, float4 v) {
    asm volatile("red.global.add.v4.f32 [%0], {%1, %2, %3, %4};"
                 :: "l"(addr), "f"(v.x), "f"(v.y), "f"(v.z), "f"(v.w) : "memory");
}
__device__ __forceinline__ void ldsm_x4(uint32_t* r, uint32_t addr) {
    asm volatile("ldmatrix.sync.aligned.m8n8.x4.shared.b16 {%0,%1,%2,%3}, [%4];"
                 : "=r"(r[0]), "=r"(r[1]), "=r"(r[2]), "=r"(r[3]) : "r"(addr));
}
__device__ __forceinline__ void mma16816(float* d, const uint32_t* a, const uint32_t* b) {
    asm volatile("mma.sync.aligned.m16n8k16.row.col.f32.bf16.bf16.f32 "
                 "{%0,%1,%2,%3}, {%4,%5,%6,%7}, {%8,%9}, {%0,%1,%2,%3};"
                 : "+f"(d[0]), "+f"(d[1]), "+f"(d[2]), "+f"(d[3])
                 : "r"(a[0]), "r"(a[1]), "r"(a[2]), "r"(a[3]), "r"(b[0]), "r"(b[1]));
}

// ================= small kernels =================
__global__ void zero_kernel() {
    const int n4 = N_NODES * HIDDEN / 4;
    float4 z = make_float4(0.f, 0.f, 0.f, 0.f);
    for (int i = blockIdx.x * blockDim.x + threadIdx.x; i < n4; i += gridDim.x * blockDim.x)
        ((float4*)g_agg)[i] = z;
}

__global__ void prep_kernel(const float* __restrict__ Wf2, const float* __restrict__ bf2,
                            const float* __restrict__ bi2, const float* __restrict__ gamma,
                            const float* __restrict__ beta, const float* __restrict__ mmean,
                            const float* __restrict__ mvar) {
    int t = threadIdx.x;
    if (t < NFILT) {
        float s = 0.f;
        for (int f = 0; f < NFILT; f++) s += Wf2[t * NFILT + f];
        g_wsum[t] = s;
    }
    if (t == 0) {
        float s = 0.f;
        for (int f = 0; f < NFILT; f++) s += bf2[f];
        g_bsum = s;
    }
    if (t < HIDDEN) {
        float sc = gamma[t] * rsqrtf(mvar[t] + 1e-3f);
        g_oscale[t] = sc;
        g_oshift[t] = (bi2[t] - mmean[t]) * sc + beta[t];
    }
}

// split W[k][n] into transposed hi/lo bf16 arrays [n][k]
__global__ void wprep_kernel(const float* __restrict__ Wi1, const float* __restrict__ Wi2) {
    int idx = blockIdx.x * blockDim.x + threadIdx.x;
    if (idx >= 2 * HIDDEN * HIDDEN) return;
    int w = idx / (HIDDEN * HIDDEN);
    int r = idx % (HIDDEN * HIDDEN);
    int n = r / HIDDEN, k = r % HIDDEN;
    float b = (w ? Wi2 : Wi1)[k * HIDDEN + n];
    __nv_bfloat16 hi = __float2bfloat16_rn(b);
    __nv_bfloat16 lo = __float2bfloat16_rn(b - __bfloat162float(hi));
    (w ? g_W2h : g_W1h)[n * HIDDEN + k] = hi;
    (w ? g_W2l : g_W1l)[n * HIDDEN + k] = lo;
}

__global__ void table_kernel(const float* __restrict__ Wf1, const float* __restrict__ bf1) {
    int t = blockIdx.x * blockDim.x + threadIdx.x;
    if (t >= TABLE_N) return;
    float w = (float)t * (CUTOFF / (float)(TABLE_N - 1));
    float sc = w * (2.0f / CUTOFF) - 1.0f;
    float s = g_bsum;
    #pragma unroll 8
    for (int g = 0; g < NFILT; g++)
        s += tanhf(sc * __ldg(&Wf1[g]) + __ldg(&bf1[g])) * g_wsum[g];
    float cut = 0.5f * (cospif(w * (1.0f / CUTOFF)) + 1.0f);
    g_table[t] = s * cut;
}

__global__ __launch_bounds__(256) void scatter_kernel(
        const float* __restrict__ x, const int* __restrict__ ei,
        const float* __restrict__ ew, int E) {
    int gw = (blockIdx.x * blockDim.x + threadIdx.x) >> 5;
    int nw = (gridDim.x * blockDim.x) >> 5;
    int lane = threadIdx.x & 31;

    for (int e0 = gw * EPW; e0 < E; e0 += nw * EPW) {
        int n = E - e0; if (n > EPW) n = EPW;
        float fs = 0.f; int row = 0, col = 0;
        if (lane < n) {
            float w = __ldg(&ew[e0 + lane]);
            row = __ldg(&ei[e0 + lane]);
            col = __ldg(&ei[E + e0 + lane]);
            float u = w * ((float)(TABLE_N - 1) / CUTOFF);
            int i = (int)u;
            if (i > TABLE_N - 2) i = TABLE_N - 2;
            float fr = u - (float)i;
            float t0 = g_table[i];
            fs = (w <= CUTOFF) ? (t0 + fr * (g_table[i + 1] - t0)) : 0.f;
        }
        float4 v[EPW]; int rows[EPW]; float fss[EPW];
        #pragma unroll
        for (int j = 0; j < EPW; j++) {
            int c = __shfl_sync(0xFFFFFFFFu, col, j);
            rows[j] = __shfl_sync(0xFFFFFFFFu, row, j);
            fss[j] = __shfl_sync(0xFFFFFFFFu, fs, j);
            if (j < n) v[j] = ((const float4*)x)[c * 32 + lane];
        }
        #pragma unroll
        for (int j = 0; j < EPW; j++) {
            if (j < n && fss[j] != 0.f) {
                float4 t = v[j]; float f = fss[j];
                t.x *= f; t.y *= f; t.z *= f; t.w *= f;
                red_add_v4(((float4*)g_agg) + rows[j] * 32 + lane, t);
            }
        }
    }
}

// ================= tensor-core (HMMA) MLP =================
// smem (bf16 elems): sAh[0,17408) sAl[17408,34816)
//   sW1h[34816..] sW1l sW2h sW2l (17408 each)
// then f32 bias/scale/shift
#define SA_H   0
#define SA_L   17408
#define SW_1H  34816
#define SW_1L  52224
#define SW_2H  69632
#define SW_2L  87040
#define SM_BF16_TOTAL 104448
#define SMEM_MMA (SM_BF16_TOTAL * 2 + 3 * 512)

// one GEMM pass: D += A(16 rows of warp) x W'(all 128 n)
__device__ __forceinline__ void gemm_pass(float acc[16][4], uint32_t aBase, uint32_t wBase,
                                          int arow, int acol, int brow, int bcol) {
    #pragma unroll
    for (int k0 = 0; k0 < 128; k0 += 16) {
        uint32_t a[4];
        ldsm_x4(a, aBase + (uint32_t)(arow * LDW + k0 + acol) * 2u);
        #pragma unroll
        for (int nt = 0; nt < 8; nt++) {
            uint32_t b[4];
            ldsm_x4(b, wBase + (uint32_t)((nt * 16 + brow) * LDW + k0 + bcol) * 2u);
            mma16816(acc[nt * 2],     a, b);
            mma16816(acc[nt * 2 + 1], a, b + 2);
        }
    }
}

__global__ __launch_bounds__(256, 1) void mlp_mma_kernel(const float* __restrict__ bi1,
                                                         float* __restrict__ out) {
    extern __shared__ __nv_bfloat16 sm[];
    float* sBias  = (float*)(sm + SM_BF16_TOTAL);
    float* sScale = sBias + 128;
    float* sShift = sBias + 256;

    int tid = threadIdx.x;
    int lane = tid & 31, wp = tid >> 5;
    int m0 = wp * 16;

    // stage split weights into padded smem
    for (int i = tid; i < 4 * 128 * 16; i += 256) {
        int a = i >> 11;            // which array
        int r = (i >> 4) & 127;     // n row
        int q = i & 15;             // 8-bf16 chunk
        const uint4* src = (const uint4*)(a == 0 ? g_W1h : a == 1 ? g_W1l :
                                          a == 2 ? g_W2h : g_W2l);
        int dst = (a == 0 ? SW_1H : a == 1 ? SW_1L : a == 2 ? SW_2H : SW_2L);
        *(uint4*)&sm[dst + r * LDW + q * 8] = src[r * 16 + q];
    }
    if (tid < 128) {
        sBias[tid]  = bi1[tid];
        sScale[tid] = g_oscale[tid];
        sShift[tid] = g_oshift[tid];
    }
    __syncthreads();

    uint32_t sb   = smem_u32(sm);
    uint32_t sbAh = sb + SA_H * 2,  sbAl = sb + SA_L * 2;
    uint32_t sb1h = sb + SW_1H * 2, sb1l = sb + SW_1L * 2;
    uint32_t sb2h = sb + SW_2H * 2, sb2l = sb + SW_2L * 2;

    // ldmatrix address components
    int arow = m0 + (lane & 15);
    int acol = (lane >> 4) << 3;
    int brow = (lane & 7) + ((lane >> 4) << 3);
    int bcol = ((lane >> 3) & 1) << 3;
    int cb = (lane & 3) * 2;        // col pair within n-tile
    int r0 = m0 + (lane >> 2);      // accumulator row (and +8)

    for (int tile = blockIdx.x; tile < N_TILES; tile += gridDim.x) {
        int rbase = tile * 128;

        // load agg tile, split into hi/lo bf16
        for (int i = tid; i < 128 * 32; i += 256) {
            int r = i >> 5, c4 = i & 31;
            int row = rbase + r;
            float4 v = make_float4(0.f, 0.f, 0.f, 0.f);
            if (row < N_NODES) v = ((const float4*)g_agg)[(size_t)row * 32 + c4];
            uint32_t h0 = bf2pack(v.x, v.y);
            uint32_t h1 = bf2pack(v.z, v.w);
            uint32_t l0 = bf2pack(v.x - __uint_as_float(h0 << 16),
                                  v.y - __uint_as_float(h0 & 0xFFFF0000u));
            uint32_t l1 = bf2pack(v.z - __uint_as_float(h1 << 16),
                                  v.w - __uint_as_float(h1 & 0xFFFF0000u));
            uint2* dh = (uint2*)&sm[SA_H + r * LDW + c4 * 4];
            uint2* dl = (uint2*)&sm[SA_L + r * LDW + c4 * 4];
            *dh = make_uint2(h0, h1);
            *dl = make_uint2(l0, l1);
        }
        __syncthreads();

        // GEMM1 (bias in accumulator init)
        float acc[16][4];
        #pragma unroll
        for (int nt = 0; nt < 16; nt++) {
            float b0 = sBias[nt * 8 + cb], b1 = sBias[nt * 8 + cb + 1];
            acc[nt][0] = b0; acc[nt][1] = b1; acc[nt][2] = b0; acc[nt][3] = b1;
        }
        gemm_pass(acc, sbAh, sb1h, arow, acol, brow, bcol);
        gemm_pass(acc, sbAh, sb1l, arow, acol, brow, bcol);
        gemm_pass(acc, sbAl, sb1h, arow, acol, brow, bcol);
        __syncwarp();

        // softplus + re-split into sA (warp-private rows)
        #pragma unroll
        for (int nt = 0; nt < 16; nt++) {
            int c = nt * 8 + cb;
            float h0 = softplus_f(acc[nt][0]);
            float h1 = softplus_f(acc[nt][1]);
            float h2 = softplus_f(acc[nt][2]);
            float h3 = softplus_f(acc[nt][3]);
            uint32_t p0 = bf2pack(h0, h1);
            uint32_t p1 = bf2pack(h2, h3);
            uint32_t q0 = bf2pack(h0 - __uint_as_float(p0 << 16),
                                  h1 - __uint_as_float(p0 & 0xFFFF0000u));
            uint32_t q1 = bf2pack(h2 - __uint_as_float(p1 << 16),
                                  h3 - __uint_as_float(p1 & 0xFFFF0000u));
            *(uint32_t*)&sm[SA_H + r0 * LDW + c]       = p0;
            *(uint32_t*)&sm[SA_L + r0 * LDW + c]       = q0;
            *(uint32_t*)&sm[SA_H + (r0 + 8) * LDW + c] = p1;
            *(uint32_t*)&sm[SA_L + (r0 + 8) * LDW + c] = q1;
        }
        __syncwarp();

        // GEMM2
        #pragma unroll
        for (int nt = 0; nt < 16; nt++) {
            acc[nt][0] = 0.f; acc[nt][1] = 0.f; acc[nt][2] = 0.f; acc[nt][3] = 0.f;
        }
        gemm_pass(acc, sbAh, sb2h, arow, acol, brow, bcol);
        gemm_pass(acc, sbAh, sb2l, arow, acol, brow, bcol);
        gemm_pass(acc, sbAl, sb2h, arow, acol, brow, bcol);

        // BN epilogue + store
        int g0 = rbase + r0;
        #pragma unroll
        for (int nt = 0; nt < 16; nt++) {
            int c = nt * 8 + cb;
            float s0 = sScale[c], s1 = sScale[c + 1];
            float t0 = sShift[c], t1 = sShift[c + 1];
            if (g0 < N_NODES)
                *(float2*)&out[(size_t)g0 * 128 + c] =
                    make_float2(acc[nt][0] * s0 + t0, acc[nt][1] * s1 + t1);
            if (g0 + 8 < N_NODES)
                *(float2*)&out[(size_t)(g0 + 8) * 128 + c] =
                    make_float2(acc[nt][2] * s0 + t0, acc[nt][3] * s1 + t1);
        }
        __syncthreads();
    }
}

extern "C" void kernel_launch(void* const* d_in, const int* in_sizes, int n_in,
                              void* d_out, int out_size) {
    const float* x     = (const float*)d_in[0];
    const int*   ei    = (const int*)  d_in[1];
    const float* ew    = (const float*)d_in[2];
    const float* Wf1   = (const float*)d_in[4];
    const float* bf1   = (const float*)d_in[5];
    const float* Wf2   = (const float*)d_in[6];
    const float* bf2   = (const float*)d_in[7];
    const float* Wi1   = (const float*)d_in[8];
    const float* bi1   = (const float*)d_in[9];
    const float* Wi2   = (const float*)d_in[10];
    const float* bi2   = (const float*)d_in[11];
    const float* gamma = (const float*)d_in[12];
    const float* beta  = (const float*)d_in[13];
    const float* mmean = (const float*)d_in[14];
    const float* mvar  = (const float*)d_in[15];
    int E = in_sizes[2];
    float* out = (float*)d_out;

    zero_kernel<<<4096, 256>>>();
    prep_kernel<<<1, 128>>>(Wf2, bf2, bi2, gamma, beta, mmean, mvar);
    wprep_kernel<<<(2 * HIDDEN * HIDDEN + 255) / 256, 256>>>(Wi1, Wi2);
    table_kernel<<<TABLE_N / 256, 256>>>(Wf1, bf1);
    scatter_kernel<<<444, 256>>>(x, ei, ew, E);   // 3 blocks/SM x 148: one wave

    cudaFuncSetAttribute(mlp_mma_kernel, cudaFuncAttributeMaxDynamicSharedMemorySize,
                         SMEM_MMA);
    mlp_mma_kernel<<<148, 256, SMEM_MMA>>>(bi1, out);
}

// round 5
// speedup vs baseline: 1.9907x; 1.0002x over previous
#include <cuda_runtime.h>
#include <cuda_bf16.h>
#include <math.h>
#include <stdint.h>

#define N_NODES 100000
#define HIDDEN  128
#define NFILT   64
#define CUTOFF  8.0f
#define TABLE_N 8192
#define EPW     8
#define N_TILES ((N_NODES + 127) / 128)  // 782
#define LDW     136                      // smem bf16 row stride (odd 16B chunks -> conflict-free ldmatrix)

// ---- device scratch (allocation-free) ----
__device__ __align__(16) float g_agg[N_NODES * HIDDEN];
__device__ float g_table[TABLE_N];
__device__ float g_wsum[NFILT];
__device__ float g_bsum;
__device__ float g_oscale[HIDDEN];
__device__ float g_oshift[HIDDEN];
// compensated bf16 weights, transposed: [n][k] with k contiguous
__device__ __align__(16) __nv_bfloat16 g_W1h[HIDDEN * HIDDEN];
__device__ __align__(16) __nv_bfloat16 g_W1l[HIDDEN * HIDDEN];
__device__ __align__(16) __nv_bfloat16 g_W2h[HIDDEN * HIDDEN];
__device__ __align__(16) __nv_bfloat16 g_W2l[HIDDEN * HIDDEN];

// ================= helpers =================
__device__ __forceinline__ uint32_t smem_u32(const void* p) {
    uint32_t a;
    asm("{ .reg .u64 t; cvta.to.shared.u64 t, %1; cvt.u32.u64 %0, t; }" : "=r"(a) : "l"(p));
    return a;
}
__device__ __forceinline__ uint32_t bf2pack(float x0, float x1) {
    uint32_t p;  // lower half = x0
    asm("cvt.rn.bf16x2.f32 %0, %1, %2;" : "=r"(p) : "f"(x1), "f"(x0));
    return p;
}
__device__ __forceinline__ float softplus_f(float x) {
    return log1pf(expf(-fabsf(x))) + fmaxf(x, 0.f);
}
__device__ __forceinline__ void red_add_v4(float4* addr, float4 v) {
    asm volatile("red.global.add.v4.f32 [%0], {%1, %2, %3, %4};"
                 :: "l"(addr), "f"(v.x), "f"(v.y), "f"(v.z), "f"(v.w) : "memory");
}
__device__ __forceinline__ void ldsm_x4(uint32_t* r, uint32_t addr) {
    asm volatile("ldmatrix.sync.aligned.m8n8.x4.shared.b16 {%0,%1,%2,%3}, [%4];"
                 : "=r"(r[0]), "=r"(r[1]), "=r"(r[2]), "=r"(r[3]) : "r"(addr));
}
__device__ __forceinline__ void mma16816(float* d, const uint32_t* a, const uint32_t* b) {
    asm volatile("mma.sync.aligned.m16n8k16.row.col.f32.bf16.bf16.f32 "
                 "{%0,%1,%2,%3}, {%4,%5,%6,%7}, {%8,%9}, {%0,%1,%2,%3};"
                 : "+f"(d[0]), "+f"(d[1]), "+f"(d[2]), "+f"(d[3])
                 : "r"(a[0]), "r"(a[1]), "r"(a[2]), "r"(a[3]), "r"(b[0]), "r"(b[1]));
}

// ================= small kernels =================
__global__ void zero_kernel() {
    const int n4 = N_NODES * HIDDEN / 4;
    float4 z = make_float4(0.f, 0.f, 0.f, 0.f);
    for (int i = blockIdx.x * blockDim.x + threadIdx.x; i < n4; i += gridDim.x * blockDim.x)
        ((float4*)g_agg)[i] = z;
}

__global__ void prep_kernel(const float* __restrict__ Wf2, const float* __restrict__ bf2,
                            const float* __restrict__ bi2, const float* __restrict__ gamma,
                            const float* __restrict__ beta, const float* __restrict__ mmean,
                            const float* __restrict__ mvar) {
    int t = threadIdx.x;
    if (t < NFILT) {
        float s = 0.f;
        for (int f = 0; f < NFILT; f++) s += Wf2[t * NFILT + f];
        g_wsum[t] = s;
    }
    if (t == 0) {
        float s = 0.f;
        for (int f = 0; f < NFILT; f++) s += bf2[f];
        g_bsum = s;
    }
    if (t < HIDDEN) {
        float sc = gamma[t] * rsqrtf(mvar[t] + 1e-3f);
        g_oscale[t] = sc;
        g_oshift[t] = (bi2[t] - mmean[t]) * sc + beta[t];
    }
}

// split W[k][n] into transposed hi/lo bf16 arrays [n][k]
__global__ void wprep_kernel(const float* __restrict__ Wi1, const float* __restrict__ Wi2) {
    int idx = blockIdx.x * blockDim.x + threadIdx.x;
    if (idx >= 2 * HIDDEN * HIDDEN) return;
    int w = idx / (HIDDEN * HIDDEN);
    int r = idx % (HIDDEN * HIDDEN);
    int n = r / HIDDEN, k = r % HIDDEN;
    float b = (w ? Wi2 : Wi1)[k * HIDDEN + n];
    __nv_bfloat16 hi = __float2bfloat16_rn(b);
    __nv_bfloat16 lo = __float2bfloat16_rn(b - __bfloat162float(hi));
    (w ? g_W2h : g_W1h)[n * HIDDEN + k] = hi;
    (w ? g_W2l : g_W1l)[n * HIDDEN + k] = lo;
}

__global__ void table_kernel(const float* __restrict__ Wf1, const float* __restrict__ bf1) {
    int t = blockIdx.x * blockDim.x + threadIdx.x;
    if (t >= TABLE_N) return;
    float w = (float)t * (CUTOFF / (float)(TABLE_N - 1));
    float sc = w * (2.0f / CUTOFF) - 1.0f;
    float s = g_bsum;
    #pragma unroll 8
    for (int g = 0; g < NFILT; g++)
        s += tanhf(sc * __ldg(&Wf1[g]) + __ldg(&bf1[g])) * g_wsum[g];
    float cut = 0.5f * (cospif(w * (1.0f / CUTOFF)) + 1.0f);
    g_table[t] = s * cut;
}

__global__ __launch_bounds__(256) void scatter_kernel(
        const float* __restrict__ x, const int* __restrict__ ei,
        const float* __restrict__ ew, int E) {
    int gw = (blockIdx.x * blockDim.x + threadIdx.x) >> 5;
    int nw = (gridDim.x * blockDim.x) >> 5;
    int lane = threadIdx.x & 31;

    for (int e0 = gw * EPW; e0 < E; e0 += nw * EPW) {
        int n = E - e0; if (n > EPW) n = EPW;
        float fs = 0.f; int row = 0, col = 0;
        if (lane < n) {
            float w = __ldg(&ew[e0 + lane]);
            row = __ldg(&ei[e0 + lane]);
            col = __ldg(&ei[E + e0 + lane]);
            float u = w * ((float)(TABLE_N - 1) / CUTOFF);
            int i = (int)u;
            if (i > TABLE_N - 2) i = TABLE_N - 2;
            float fr = u - (float)i;
            float t0 = g_table[i];
            fs = (w <= CUTOFF) ? (t0 + fr * (g_table[i + 1] - t0)) : 0.f;
        }
        float4 v[EPW]; int rows[EPW]; float fss[EPW];
        #pragma unroll
        for (int j = 0; j < EPW; j++) {
            int c = __shfl_sync(0xFFFFFFFFu, col, j);
            rows[j] = __shfl_sync(0xFFFFFFFFu, row, j);
            fss[j] = __shfl_sync(0xFFFFFFFFu, fs, j);
            if (j < n) v[j] = ((const float4*)x)[c * 32 + lane];
        }
        #pragma unroll
        for (int j = 0; j < EPW; j++) {
            if (j < n && fss[j] != 0.f) {
                float4 t = v[j]; float f = fss[j];
                t.x *= f; t.y *= f; t.z *= f; t.w *= f;
                red_add_v4(((float4*)g_agg) + rows[j] * 32 + lane, t);
            }
        }
    }
}

// ================= tensor-core (HMMA) MLP =================
// smem (bf16 elems): sAh[0,17408) sAl[17408,34816)
//   sW1h[34816..] sW1l sW2h sW2l (17408 each)
// then f32 bias/scale/shift
#define SA_H   0
#define SA_L   17408
#define SW_1H  34816
#define SW_1L  52224
#define SW_2H  69632
#define SW_2L  87040
#define SM_BF16_TOTAL 104448
#define SMEM_MMA (SM_BF16_TOTAL * 2 + 3 * 512)

// one GEMM pass: D += A(16 rows of warp) x W'(all 128 n)
__device__ __forceinline__ void gemm_pass(float acc[16][4], uint32_t aBase, uint32_t wBase,
                                          int arow, int acol, int brow, int bcol) {
    #pragma unroll
    for (int k0 = 0; k0 < 128; k0 += 16) {
        uint32_t a[4];
        ldsm_x4(a, aBase + (uint32_t)(arow * LDW + k0 + acol) * 2u);
        #pragma unroll
        for (int nt = 0; nt < 8; nt++) {
            uint32_t b[4];
            ldsm_x4(b, wBase + (uint32_t)((nt * 16 + brow) * LDW + k0 + bcol) * 2u);
            mma16816(acc[nt * 2],     a, b);
            mma16816(acc[nt * 2 + 1], a, b + 2);
        }
    }
}

__global__ __launch_bounds__(256, 1) void mlp_mma_kernel(const float* __restrict__ bi1,
                                                         float* __restrict__ out) {
    extern __shared__ __nv_bfloat16 sm[];
    float* sBias  = (float*)(sm + SM_BF16_TOTAL);
    float* sScale = sBias + 128;
    float* sShift = sBias + 256;

    int tid = threadIdx.x;
    int lane = tid & 31, wp = tid >> 5;
    int m0 = wp * 16;

    // stage split weights into padded smem
    for (int i = tid; i < 4 * 128 * 16; i += 256) {
        int a = i >> 11;            // which array
        int r = (i >> 4) & 127;     // n row
        int q = i & 15;             // 8-bf16 chunk
        const uint4* src = (const uint4*)(a == 0 ? g_W1h : a == 1 ? g_W1l :
                                          a == 2 ? g_W2h : g_W2l);
        int dst = (a == 0 ? SW_1H : a == 1 ? SW_1L : a == 2 ? SW_2H : SW_2L);
        *(uint4*)&sm[dst + r * LDW + q * 8] = src[r * 16 + q];
    }
    if (tid < 128) {
        sBias[tid]  = bi1[tid];
        sScale[tid] = g_oscale[tid];
        sShift[tid] = g_oshift[tid];
    }
    __syncthreads();

    uint32_t sb   = smem_u32(sm);
    uint32_t sbAh = sb + SA_H * 2,  sbAl = sb + SA_L * 2;
    uint32_t sb1h = sb + SW_1H * 2, sb1l = sb + SW_1L * 2;
    uint32_t sb2h = sb + SW_2H * 2, sb2l = sb + SW_2L * 2;

    // ldmatrix address components
    int arow = m0 + (lane & 15);
    int acol = (lane >> 4) << 3;
    int brow = (lane & 7) + ((lane >> 4) << 3);
    int bcol = ((lane >> 3) & 1) << 3;
    int cb = (lane & 3) * 2;        // col pair within n-tile
    int r0 = m0 + (lane >> 2);      // accumulator row (and +8)

    for (int tile = blockIdx.x; tile < N_TILES; tile += gridDim.x) {
        int rbase = tile * 128;

        // load agg tile, split into hi/lo bf16
        for (int i = tid; i < 128 * 32; i += 256) {
            int r = i >> 5, c4 = i & 31;
            int row = rbase + r;
            float4 v = make_float4(0.f, 0.f, 0.f, 0.f);
            if (row < N_NODES) v = ((const float4*)g_agg)[(size_t)row * 32 + c4];
            uint32_t h0 = bf2pack(v.x, v.y);
            uint32_t h1 = bf2pack(v.z, v.w);
            uint32_t l0 = bf2pack(v.x - __uint_as_float(h0 << 16),
                                  v.y - __uint_as_float(h0 & 0xFFFF0000u));
            uint32_t l1 = bf2pack(v.z - __uint_as_float(h1 << 16),
                                  v.w - __uint_as_float(h1 & 0xFFFF0000u));
            uint2* dh = (uint2*)&sm[SA_H + r * LDW + c4 * 4];
            uint2* dl = (uint2*)&sm[SA_L + r * LDW + c4 * 4];
            *dh = make_uint2(h0, h1);
            *dl = make_uint2(l0, l1);
        }
        __syncthreads();

        // GEMM1 (bias in accumulator init)
        float acc[16][4];
        #pragma unroll
        for (int nt = 0; nt < 16; nt++) {
            float b0 = sBias[nt * 8 + cb], b1 = sBias[nt * 8 + cb + 1];
            acc[nt][0] = b0; acc[nt][1] = b1; acc[nt][2] = b0; acc[nt][3] = b1;
        }
        gemm_pass(acc, sbAh, sb1h, arow, acol, brow, bcol);
        gemm_pass(acc, sbAh, sb1l, arow, acol, brow, bcol);
        gemm_pass(acc, sbAl, sb1h, arow, acol, brow, bcol);
        __syncwarp();

        // softplus + re-split into sA (warp-private rows)
        #pragma unroll
        for (int nt = 0; nt < 16; nt++) {
            int c = nt * 8 + cb;
            float h0 = softplus_f(acc[nt][0]);
            float h1 = softplus_f(acc[nt][1]);
            float h2 = softplus_f(acc[nt][2]);
            float h3 = softplus_f(acc[nt][3]);
            uint32_t p0 = bf2pack(h0, h1);
            uint32_t p1 = bf2pack(h2, h3);
            uint32_t q0 = bf2pack(h0 - __uint_as_float(p0 << 16),
                                  h1 - __uint_as_float(p0 & 0xFFFF0000u));
            uint32_t q1 = bf2pack(h2 - __uint_as_float(p1 << 16),
                                  h3 - __uint_as_float(p1 & 0xFFFF0000u));
            *(uint32_t*)&sm[SA_H + r0 * LDW + c]       = p0;
            *(uint32_t*)&sm[SA_L + r0 * LDW + c]       = q0;
            *(uint32_t*)&sm[SA_H + (r0 + 8) * LDW + c] = p1;
            *(uint32_t*)&sm[SA_L + (r0 + 8) * LDW + c] = q1;
        }
        __syncwarp();

        // GEMM2
        #pragma unroll
        for (int nt = 0; nt < 16; nt++) {
            acc[nt][0] = 0.f; acc[nt][1] = 0.f; acc[nt][2] = 0.f; acc[nt][3] = 0.f;
        }
        gemm_pass(acc, sbAh, sb2h, arow, acol, brow, bcol);
        gemm_pass(acc, sbAh, sb2l, arow, acol, brow, bcol);
        gemm_pass(acc, sbAl, sb2h, arow, acol, brow, bcol);

        // BN epilogue + store
        int g0 = rbase + r0;
        #pragma unroll
        for (int nt = 0; nt < 16; nt++) {
            int c = nt * 8 + cb;
            float s0 = sScale[c], s1 = sScale[c + 1];
            float t0 = sShift[c], t1 = sShift[c + 1];
            if (g0 < N_NODES)
                *(float2*)&out[(size_t)g0 * 128 + c] =
                    make_float2(acc[nt][0] * s0 + t0, acc[nt][1] * s1 + t1);
            if (g0 + 8 < N_NODES)
                *(float2*)&out[(size_t)(g0 + 8) * 128 + c] =
                    make_float2(acc[nt][2] * s0 + t0, acc[nt][3] * s1 + t1);
        }
        __syncthreads();
    }
}

extern "C" void kernel_launch(void* const* d_in, const int* in_sizes, int n_in,
                              void* d_out, int out_size) {
    const float* x     = (const float*)d_in[0];
    const int*   ei    = (const int*)  d_in[1];
    const float* ew    = (const float*)d_in[2];
    const float* Wf1   = (const float*)d_in[4];
    const float* bf1   = (const float*)d_in[5];
    const float* Wf2   = (const float*)d_in[6];
    const float* bf2   = (const float*)d_in[7];
    const float* Wi1   = (const float*)d_in[8];
    const float* bi1   = (const float*)d_in[9];
    const float* Wi2   = (const float*)d_in[10];
    const float* bi2   = (const float*)d_in[11];
    const float* gamma = (const float*)d_in[12];
    const float* beta  = (const float*)d_in[13];
    const float* mmean = (const float*)d_in[14];
    const float* mvar  = (const float*)d_in[15];
    int E = in_sizes[2];
    float* out = (float*)d_out;

    zero_kernel<<<4096, 256>>>();
    prep_kernel<<<1, 128>>>(Wf2, bf2, bi2, gamma, beta, mmean, mvar);
    wprep_kernel<<<(2 * HIDDEN * HIDDEN + 255) / 256, 256>>>(Wi1, Wi2);
    table_kernel<<<TABLE_N / 256, 256>>>(Wf1, bf1);
    scatter_kernel<<<444, 256>>>(x, ei, ew, E);   // 3 blocks/SM x 148: one wave

    cudaFuncSetAttribute(mlp_mma_kernel, cudaFuncAttributeMaxDynamicSharedMemorySize,
                         SMEM_MMA);
    mlp_mma_kernel<<<148, 256, SMEM_MMA>>>(bi1, out);
}

// round 7
// speedup vs baseline: 2.1343x; 1.0721x over previous
#include <cuda_runtime.h>
#include <cuda_bf16.h>
#include <math.h>
#include <stdint.h>

#define N_NODES 100000
#define N_EDGES_MAX 1600000
#define HIDDEN  128
#define NFILT   64
#define CUTOFF  8.0f
#define TABLE_N 8192
#define N_TILES ((N_NODES + 127) / 128)  // 782
#define LDW     136                      // smem bf16 row stride
#define NB      256                      // scan chunks
#define CH      391                      // ceil(100000/256)

// ---- device scratch (allocation-free) ----
__device__ __align__(16) float g_agg[N_NODES * HIDDEN];
__device__ float g_table[TABLE_N];
__device__ float g_wsum[NFILT];
__device__ float g_bsum;
__device__ float g_oscale[HIDDEN];
__device__ float g_oshift[HIDDEN];
__device__ __align__(16) __nv_bfloat16 g_W1h[HIDDEN * HIDDEN];
__device__ __align__(16) __nv_bfloat16 g_W1l[HIDDEN * HIDDEN];
__device__ __align__(16) __nv_bfloat16 g_W2h[HIDDEN * HIDDEN];
__device__ __align__(16) __nv_bfloat16 g_W2l[HIDDEN * HIDDEN];
// CSR
__device__ int   g_cnt[N_NODES];
__device__ int   g_rowptr[N_NODES + 1];
__device__ int   g_cur[N_NODES];
__device__ int   g_part[NB];
__device__ int   g_poff[NB];
__device__ __align__(8) uint2 g_eord[N_EDGES_MAX];   // (col, fs bits)

// ================= helpers =================
__device__ __forceinline__ uint32_t smem_u32(const void* p) {
    uint32_t a;
    asm("{ .reg .u64 t; cvta.to.shared.u64 t, %1; cvt.u32.u64 %0, t; }" : "=r"(a) : "l"(p));
    return a;
}
__device__ __forceinline__ uint32_t bf2pack(float x0, float x1) {
    uint32_t p;  // lower half = x0
    asm("cvt.rn.bf16x2.f32 %0, %1, %2;" : "=r"(p) : "f"(x1), "f"(x0));
    return p;
}
__device__ __forceinline__ float softplus_f(float x) {
    return log1pf(expf(-fabsf(x))) + fmaxf(x, 0.f);
}
__device__ __forceinline__ void ldsm_x4(uint32_t* r, uint32_t addr) {
    asm volatile("ldmatrix.sync.aligned.m8n8.x4.shared.b16 {%0,%1,%2,%3}, [%4];"
                 : "=r"(r[0]), "=r"(r[1]), "=r"(r[2]), "=r"(r[3]) : "r"(addr));
}
__device__ __forceinline__ void mma16816(float* d, const uint32_t* a, const uint32_t* b) {
    asm volatile("mma.sync.aligned.m16n8k16.row.col.f32.bf16.bf16.f32 "
                 "{%0,%1,%2,%3}, {%4,%5,%6,%7}, {%8,%9}, {%0,%1,%2,%3};"
                 : "+f"(d[0]), "+f"(d[1]), "+f"(d[2]), "+f"(d[3])
                 : "r"(a[0]), "r"(a[1]), "r"(a[2]), "r"(a[3]), "r"(b[0]), "r"(b[1]));
}

// ================= small kernels =================
__global__ void prep_kernel(const float* __restrict__ Wf2, const float* __restrict__ bf2,
                            const float* __restrict__ bi2, const float* __restrict__ gamma,
                            const float* __restrict__ beta, const float* __restrict__ mmean,
                            const float* __restrict__ mvar) {
    int t = threadIdx.x;
    if (t < NFILT) {
        float s = 0.f;
        for (int f = 0; f < NFILT; f++) s += Wf2[t * NFILT + f];
        g_wsum[t] = s;
    }
    if (t == 0) {
        float s = 0.f;
        for (int f = 0; f < NFILT; f++) s += bf2[f];
        g_bsum = s;
    }
    if (t < HIDDEN) {
        float sc = gamma[t] * rsqrtf(mvar[t] + 1e-3f);
        g_oscale[t] = sc;
        g_oshift[t] = (bi2[t] - mmean[t]) * sc + beta[t];
    }
}

__global__ void wprep_kernel(const float* __restrict__ Wi1, const float* __restrict__ Wi2) {
    int idx = blockIdx.x * blockDim.x + threadIdx.x;
    if (idx >= 2 * HIDDEN * HIDDEN) return;
    int w = idx / (HIDDEN * HIDDEN);
    int r = idx % (HIDDEN * HIDDEN);
    int n = r / HIDDEN, k = r % HIDDEN;
    float b = (w ? Wi2 : Wi1)[k * HIDDEN + n];
    __nv_bfloat16 hi = __float2bfloat16_rn(b);
    __nv_bfloat16 lo = __float2bfloat16_rn(b - __bfloat162float(hi));
    (w ? g_W2h : g_W1h)[n * HIDDEN + k] = hi;
    (w ? g_W2l : g_W1l)[n * HIDDEN + k] = lo;
}

__global__ void table_kernel(const float* __restrict__ Wf1, const float* __restrict__ bf1) {
    int t = blockIdx.x * blockDim.x + threadIdx.x;
    if (t >= TABLE_N) return;
    float w = (float)t * (CUTOFF / (float)(TABLE_N - 1));
    float sc = w * (2.0f / CUTOFF) - 1.0f;
    float s = g_bsum;
    #pragma unroll 8
    for (int g = 0; g < NFILT; g++)
        s += tanhf(sc * __ldg(&Wf1[g]) + __ldg(&bf1[g])) * g_wsum[g];
    float cut = 0.5f * (cospif(w * (1.0f / CUTOFF)) + 1.0f);
    g_table[t] = s * cut;
}

// ================= CSR build =================
__global__ void zcnt_kernel() {
    int i = blockIdx.x * blockDim.x + threadIdx.x;
    if (i < N_NODES) g_cnt[i] = 0;
}
__global__ void hist_kernel(const int* __restrict__ ei, int E) {
    int e = blockIdx.x * blockDim.x + threadIdx.x;
    if (e < E) atomicAdd(&g_cnt[ei[e]], 1);
}
// per-chunk reduce
__global__ void scan1_kernel() {
    __shared__ int red[256];
    int b = blockIdx.x, t = threadIdx.x;
    int base = b * CH;
    int s = 0;
    for (int i = t; i < CH; i += 256) {
        int gi = base + i;
        s += (gi < N_NODES) ? g_cnt[gi] : 0;
    }
    red[t] = s;
    __syncthreads();
    for (int d = 128; d > 0; d >>= 1) {
        if (t < d) red[t] += red[t + d];
        __syncthreads();
    }
    if (t == 0) g_part[b] = red[0];
}
// exclusive scan of 256 partials
__global__ void scan2_kernel() {
    __shared__ int s[256];
    int t = threadIdx.x;
    s[t] = g_part[t];
    __syncthreads();
    for (int d = 1; d < 256; d <<= 1) {
        int v = (t >= d) ? s[t - d] : 0;
        __syncthreads();
        s[t] += v;
        __syncthreads();
    }
    g_poff[t] = s[t] - g_part[t];   // exclusive
}
// per-chunk scan + offset -> rowptr, cur
__global__ void scan3_kernel(int E) {
    __shared__ int s[512];
    int b = blockIdx.x, t = threadIdx.x;
    int base = b * CH;
    int gi = base + t;
    int c = (t < CH && gi < N_NODES) ? g_cnt[gi] : 0;
    s[t] = c;
    __syncthreads();
    for (int d = 1; d < 512; d <<= 1) {
        int v = (t >= d) ? s[t - d] : 0;
        __syncthreads();
        s[t] += v;
        __syncthreads();
    }
    if (t < CH && gi < N_NODES) {
        int ex = g_poff[b] + s[t] - c;   // exclusive prefix
        g_rowptr[gi] = ex;
        g_cur[gi] = ex;
    }
    if (b == NB - 1 && t == 0) g_rowptr[N_NODES] = E;
}
__global__ void reorder_kernel(const int* __restrict__ ei, const float* __restrict__ ew,
                               int E) {
    int e = blockIdx.x * blockDim.x + threadIdx.x;
    if (e >= E) return;
    int row = ei[e], col = ei[E + e];
    float w = ew[e];
    float fs = 0.f;
    if (w <= CUTOFF) {
        float u = w * ((float)(TABLE_N - 1) / CUTOFF);
        int i = (int)u;
        if (i > TABLE_N - 2) i = TABLE_N - 2;
        float fr = u - (float)i;
        float t0 = g_table[i];
        fs = t0 + fr * (g_table[i + 1] - t0);
    }
    int pos = atomicAdd(&g_cur[row], 1);
    g_eord[pos] = make_uint2((uint32_t)col, __float_as_uint(fs));
}

// ================= aggregate: one warp per node, no atomics =================
__global__ __launch_bounds__(256) void aggregate_kernel(const float* __restrict__ x) {
    int node = (blockIdx.x * blockDim.x + threadIdx.x) >> 5;
    int lane = threadIdx.x & 31;
    if (node >= N_NODES) return;
    int s = g_rowptr[node], e = g_rowptr[node + 1];
    float4 acc = make_float4(0.f, 0.f, 0.f, 0.f);
    for (int b = s; b < e; b += 8) {
        int n = e - b; if (n > 8) n = 8;
        uint2 ed = make_uint2(0u, 0u);
        if (lane < n) ed = g_eord[b + lane];
        float4 v[8]; float fss[8];
        #pragma unroll
        for (int j = 0; j < 8; j++) {
            int c = __shfl_sync(0xFFFFFFFFu, (int)ed.x, j);
            uint32_t f = __shfl_sync(0xFFFFFFFFu, ed.y, j);
            fss[j] = __uint_as_float(f);
            if (j < n) v[j] = ((const float4*)x)[(size_t)c * 32 + lane];
        }
        #pragma unroll
        for (int j = 0; j < 8; j++) {
            if (j < n) {
                float f = fss[j];
                acc.x += v[j].x * f; acc.y += v[j].y * f;
                acc.z += v[j].z * f; acc.w += v[j].w * f;
            }
        }
    }
    ((float4*)g_agg)[(size_t)node * 32 + lane] = acc;
}

// ================= tensor-core (HMMA) MLP =================
#define SA_H   0
#define SA_L   17408
#define SW_1H  34816
#define SW_1L  52224
#define SW_2H  69632
#define SW_2L  87040
#define SM_BF16_TOTAL 104448
#define SMEM_MMA (SM_BF16_TOTAL * 2 + 3 * 512)

// pass: D += A x W  (single A source)
__device__ __forceinline__ void gemm_pass(float acc[16][4], uint32_t aBase, uint32_t wBase,
                                          int arow, int acol, int brow, int bcol) {
    #pragma unroll
    for (int k0 = 0; k0 < 128; k0 += 16) {
        uint32_t a[4];
        ldsm_x4(a, aBase + (uint32_t)(arow * LDW + k0 + acol) * 2u);
        #pragma unroll
        for (int nt = 0; nt < 8; nt++) {
            uint32_t b[4];
            ldsm_x4(b, wBase + (uint32_t)((nt * 16 + brow) * LDW + k0 + bcol) * 2u);
            mma16816(acc[nt * 2],     a, b);
            mma16816(acc[nt * 2 + 1], a, b + 2);
        }
    }
}
// dual pass: D += (Ah + Al) x W, sharing each W fragment load
__device__ __forceinline__ void gemm_dual(float acc[16][4], uint32_t aH, uint32_t aL,
                                          uint32_t wBase,
                                          int arow, int acol, int brow, int bcol) {
    #pragma unroll
    for (int k0 = 0; k0 < 128; k0 += 16) {
        uint32_t ah[4], al[4];
        ldsm_x4(ah, aH + (uint32_t)(arow * LDW + k0 + acol) * 2u);
        ldsm_x4(al, aL + (uint32_t)(arow * LDW + k0 + acol) * 2u);
        #pragma unroll
        for (int nt = 0; nt < 8; nt++) {
            uint32_t b[4];
            ldsm_x4(b, wBase + (uint32_t)((nt * 16 + brow) * LDW + k0 + bcol) * 2u);
            mma16816(acc[nt * 2],     ah, b);
            mma16816(acc[nt * 2 + 1], ah, b + 2);
            mma16816(acc[nt * 2],     al, b);
            mma16816(acc[nt * 2 + 1], al, b + 2);
        }
    }
}

__global__ __launch_bounds__(256, 1) void mlp_mma_kernel(const float* __restrict__ bi1,
                                                         float* __restrict__ out) {
    extern __shared__ __nv_bfloat16 sm[];
    float* sBias  = (float*)(sm + SM_BF16_TOTAL);
    float* sScale = sBias + 128;
    float* sShift = sBias + 256;

    int tid = threadIdx.x;
    int lane = tid & 31, wp = tid >> 5;
    int m0 = wp * 16;

    for (int i = tid; i < 4 * 128 * 16; i += 256) {
        int a = i >> 11;
        int r = (i >> 4) & 127;
        int q = i & 15;
        const uint4* src = (const uint4*)(a == 0 ? g_W1h : a == 1 ? g_W1l :
                                          a == 2 ? g_W2h : g_W2l);
        int dst = (a == 0 ? SW_1H : a == 1 ? SW_1L : a == 2 ? SW_2H : SW_2L);
        *(uint4*)&sm[dst + r * LDW + q * 8] = src[r * 16 + q];
    }
    if (tid < 128) {
        sBias[tid]  = bi1[tid];
        sScale[tid] = g_oscale[tid];
        sShift[tid] = g_oshift[tid];
    }
    __syncthreads();

    uint32_t sb   = smem_u32(sm);
    uint32_t sbAh = sb + SA_H * 2,  sbAl = sb + SA_L * 2;
    uint32_t sb1h = sb + SW_1H * 2, sb1l = sb + SW_1L * 2;
    uint32_t sb2h = sb + SW_2H * 2, sb2l = sb + SW_2L * 2;

    int arow = m0 + (lane & 15);
    int acol = (lane >> 4) << 3;
    int brow = (lane & 7) + ((lane >> 4) << 3);
    int bcol = ((lane >> 3) & 1) << 3;
    int cb = (lane & 3) * 2;
    int r0 = m0 + (lane >> 2);

    for (int tile = blockIdx.x; tile < N_TILES; tile += gridDim.x) {
        int rbase = tile * 128;

        for (int i = tid; i < 128 * 32; i += 256) {
            int r = i >> 5, c4 = i & 31;
            int row = rbase + r;
            float4 v = make_float4(0.f, 0.f, 0.f, 0.f);
            if (row < N_NODES) v = ((const float4*)g_agg)[(size_t)row * 32 + c4];
            uint32_t h0 = bf2pack(v.x, v.y);
            uint32_t h1 = bf2pack(v.z, v.w);
            uint32_t l0 = bf2pack(v.x - __uint_as_float(h0 << 16),
                                  v.y - __uint_as_float(h0 & 0xFFFF0000u));
            uint32_t l1 = bf2pack(v.z - __uint_as_float(h1 << 16),
                                  v.w - __uint_as_float(h1 & 0xFFFF0000u));
            *(uint2*)&sm[SA_H + r * LDW + c4 * 4] = make_uint2(h0, h1);
            *(uint2*)&sm[SA_L + r * LDW + c4 * 4] = make_uint2(l0, l1);
        }
        __syncthreads();

        // GEMM1: (Ah+Al)*W1h + Ah*W1l, bias in acc init
        float acc[16][4];
        #pragma unroll
        for (int nt = 0; nt < 16; nt++) {
            float b0 = sBias[nt * 8 + cb], b1 = sBias[nt * 8 + cb + 1];
            acc[nt][0] = b0; acc[nt][1] = b1; acc[nt][2] = b0; acc[nt][3] = b1;
        }
        gemm_dual(acc, sbAh, sbAl, sb1h, arow, acol, brow, bcol);
        gemm_pass(acc, sbAh, sb1l, arow, acol, brow, bcol);
        __syncwarp();

        #pragma unroll
        for (int nt = 0; nt < 16; nt++) {
            int c = nt * 8 + cb;
            float h0 = softplus_f(acc[nt][0]);
            float h1 = softplus_f(acc[nt][1]);
            float h2 = softplus_f(acc[nt][2]);
            float h3 = softplus_f(acc[nt][3]);
            uint32_t p0 = bf2pack(h0, h1);
            uint32_t p1 = bf2pack(h2, h3);
            uint32_t q0 = bf2pack(h0 - __uint_as_float(p0 << 16),
                                  h1 - __uint_as_float(p0 & 0xFFFF0000u));
            uint32_t q1 = bf2pack(h2 - __uint_as_float(p1 << 16),
                                  h3 - __uint_as_float(p1 & 0xFFFF0000u));
            *(uint32_t*)&sm[SA_H + r0 * LDW + c]       = p0;
            *(uint32_t*)&sm[SA_L + r0 * LDW + c]       = q0;
            *(uint32_t*)&sm[SA_H + (r0 + 8) * LDW + c] = p1;
            *(uint32_t*)&sm[SA_L + (r0 + 8) * LDW + c] = q1;
        }
        __syncwarp();

        #pragma unroll
        for (int nt = 0; nt < 16; nt++) {
            acc[nt][0] = 0.f; acc[nt][1] = 0.f; acc[nt][2] = 0.f; acc[nt][3] = 0.f;
        }
        gemm_dual(acc, sbAh, sbAl, sb2h, arow, acol, brow, bcol);
        gemm_pass(acc, sbAh, sb2l, arow, acol, brow, bcol);

        int g0 = rbase + r0;
        #pragma unroll
        for (int nt = 0; nt < 16; nt++) {
            int c = nt * 8 + cb;
            float s0 = sScale[c], s1 = sScale[c + 1];
            float t0 = sShift[c], t1 = sShift[c + 1];
            if (g0 < N_NODES)
                *(float2*)&out[(size_t)g0 * 128 + c] =
                    make_float2(acc[nt][0] * s0 + t0, acc[nt][1] * s1 + t1);
            if (g0 + 8 < N_NODES)
                *(float2*)&out[(size_t)(g0 + 8) * 128 + c] =
                    make_float2(acc[nt][2] * s0 + t0, acc[nt][3] * s1 + t1);
        }
        __syncthreads();
    }
}

extern "C" void kernel_launch(void* const* d_in, const int* in_sizes, int n_in,
                              void* d_out, int out_size) {
    const float* x     = (const float*)d_in[0];
    const int*   ei    = (const int*)  d_in[1];
    const float* ew    = (const float*)d_in[2];
    const float* Wf1   = (const float*)d_in[4];
    const float* bf1   = (const float*)d_in[5];
    const float* Wf2   = (const float*)d_in[6];
    const float* bf2   = (const float*)d_in[7];
    const float* Wi1   = (const float*)d_in[8];
    const float* bi1   = (const float*)d_in[9];
    const float* Wi2   = (const float*)d_in[10];
    const float* bi2   = (const float*)d_in[11];
    const float* gamma = (const float*)d_in[12];
    const float* beta  = (const float*)d_in[13];
    const float* mmean = (const float*)d_in[14];
    const float* mvar  = (const float*)d_in[15];
    int E = in_sizes[2];
    float* out = (float*)d_out;

    prep_kernel<<<1, 128>>>(Wf2, bf2, bi2, gamma, beta, mmean, mvar);
    table_kernel<<<TABLE_N / 256, 256>>>(Wf1, bf1);
    wprep_kernel<<<(2 * HIDDEN * HIDDEN + 255) / 256, 256>>>(Wi1, Wi2);

    zcnt_kernel<<<(N_NODES + 255) / 256, 256>>>();
    hist_kernel<<<(E + 255) / 256, 256>>>(ei, E);
    scan1_kernel<<<NB, 256>>>();
    scan2_kernel<<<1, 256>>>();
    scan3_kernel<<<NB, 512>>>(E);
    reorder_kernel<<<(E + 255) / 256, 256>>>(ei, ew, E);

    aggregate_kernel<<<(N_NODES * 32 + 255) / 256, 256>>>(x);

    cudaFuncSetAttribute(mlp_mma_kernel, cudaFuncAttributeMaxDynamicSharedMemorySize,
                         SMEM_MMA);
    mlp_mma_kernel<<<148, 256, SMEM_MMA>>>(bi1, out);
}